// round 6
// baseline (speedup 1.0000x reference)
#include <cuda_runtime.h>
#include <cuda_fp16.h>
#include <math.h>
#include <stdint.h>

#define B 8192
#define D 256
#define P 4096
#define MASKW 256                      /* B/32 mask words per row */
#define LDC 136                        /* chunk smem stride in halves (128+8) */
#define CHUNK_BYTES (128*LDC*2)        /* 34816 per matrix per stage */
#define STAGE_BYTES (2*CHUNK_BYTES)    /* A+B: 69632 */
#define GEMM_SMEM   (2*STAGE_BYTES)    /* 139264 */

// ---------------- device globals (no runtime allocation allowed) -------------
__device__ float    g_E[B*D];                    // normalized fp32 (8 MB)
__device__ __half   g_Eh[B*D];                   // normalized fp16 (4 MB)
__device__ unsigned g_mask[(size_t)B*MASKW];     // B x B bitmap (8 MB)
__device__ int      g_flags[B];
__device__ int      g_rows[B];
__device__ int      g_NR;
__device__ unsigned short g_KEY[(size_t)B*B];    // u16 ordered cos keys (128 MB)
__device__ float    g_S[B];
__device__ float    g_pos[P];

// ---------------- helpers ----------------------------------------------------
__device__ __forceinline__ uint32_t smem_u32(const void* p) {
    uint32_t a;
    asm("{ .reg .u64 t; cvta.to.shared.u64 t, %1; cvt.u32.u64 %0, t; }" : "=r"(a) : "l"(p));
    return a;
}
__device__ __forceinline__ void cp_async16(uint32_t dst, const void* src) {
    asm volatile("cp.async.cg.shared.global [%0], [%1], 16;" :: "r"(dst), "l"(src));
}
__device__ __forceinline__ void ldsm_x4(uint32_t* r, uint32_t addr) {
    asm volatile("ldmatrix.sync.aligned.m8n8.x4.shared.b16 {%0,%1,%2,%3}, [%4];"
        : "=r"(r[0]), "=r"(r[1]), "=r"(r[2]), "=r"(r[3]) : "r"(addr));
}
__device__ __forceinline__ void mma16816(float* c, const uint32_t* a, const uint32_t* b) {
    asm volatile(
        "mma.sync.aligned.m16n8k16.row.col.f32.f16.f16.f32 "
        "{%0,%1,%2,%3}, {%4,%5,%6,%7}, {%8,%9}, {%0,%1,%2,%3};"
        : "+f"(c[0]), "+f"(c[1]), "+f"(c[2]), "+f"(c[3])
        : "r"(a[0]), "r"(a[1]), "r"(a[2]), "r"(a[3]), "r"(b[0]), "r"(b[1]));
}
// order-preserving u16 key of fp16 value
__device__ __forceinline__ unsigned short enc_key(float c) {
    unsigned short h = __half_as_ushort(__float2half_rn(c));
    return (h & 0x8000) ? (unsigned short)(~h) : (unsigned short)(h | 0x8000);
}
__device__ __forceinline__ float dec_key(unsigned k) {
    unsigned short h = (k & 0x8000u) ? (unsigned short)(k & 0x7FFFu) : (unsigned short)(~k);
    return __half2float(__ushort_as_half(h));
}
#define KEY_MASKED 0x03FFu   /* enc(-inf): decodes to -inf, exp -> 0 */

// warp-aggregated shared histogram add (conflict-degree-proof)
__device__ __forceinline__ void hist_add(unsigned* hist, unsigned bucket, int lane) {
    unsigned m = __match_any_sync(0xffffffffu, bucket);
    if ((m & ((1u << lane) - 1u)) == 0u && bucket != 0xFFFFFFFFu)
        atomicAdd(&hist[bucket], __popc(m));
}

// 256-bin inclusive scan; returns cin for this thread's bin; 2 barriers.
__device__ __forceinline__ unsigned scan256(unsigned* hist, unsigned* wsum,
                                            int t, int lane, int wid) {
    unsigned h = hist[t];
    unsigned x = h;
    #pragma unroll
    for (int o = 1; o < 32; o <<= 1) {
        unsigned y = __shfl_up_sync(0xffffffffu, x, o);
        if (lane >= o) x += y;
    }
    if (lane == 31) wsum[wid] = x;
    __syncthreads();
    if (t < 8) {
        unsigned w = wsum[t];
        #pragma unroll
        for (int o = 1; o < 8; o <<= 1) {
            unsigned y = __shfl_up_sync(0xffu, w, o);
            if (t >= o) w += y;
        }
        wsum[t] = w;
    }
    __syncthreads();
    return x + (wid ? wsum[wid-1] : 0u);
}

// ---------------- clear ------------------------------------------------------
__global__ void k_clear() {
    int idx = blockIdx.x * 256 + threadIdx.x;
    if (idx < B*MASKW) g_mask[idx] = 0u;
    if (idx < B)       g_flags[idx] = 0;
    if (idx == 0)      g_NR = 0;
}

// ---------------- normalize + fp16 copy + diagonal mask ----------------------
__global__ void k_normalize(const float* __restrict__ emb) {
    int r = blockIdx.x, t = threadIdx.x;
    __shared__ float red[256];
    float x = emb[r*D + t];
    red[t] = x * x;
    __syncthreads();
    for (int o = 128; o > 0; o >>= 1) { if (t < o) red[t] += red[t+o]; __syncthreads(); }
    float nrm = fmaxf(sqrtf(red[0]), 1e-8f);
    float e = x / nrm;
    g_E [r*D + t] = e;
    g_Eh[r*D + t] = __float2half_rn(e);
    if (t == 0) g_mask[(size_t)r*MASKW + (r>>5)] = (1u << (r & 31));
}

// ---------------- pairs: exact fp32 pos, mask bits, row flags ----------------
__global__ void k_pairs(const int* __restrict__ pp) {
    int w = threadIdx.x >> 5, lane = threadIdx.x & 31;
    int p = blockIdx.x * 8 + w;
    if (p >= P) return;
    int i = pp[p*2], j = pp[p*2+1];
    const float* ei = &g_E[(size_t)i*D];
    const float* ej = &g_E[(size_t)j*D];
    float s = 0.f;
    #pragma unroll
    for (int q = 0; q < 8; q++) { int d = lane + 32*q; s += ei[d] * ej[d]; }
    #pragma unroll
    for (int o = 16; o > 0; o >>= 1) s += __shfl_xor_sync(0xffffffffu, s, o);
    if (lane == 0) {
        g_pos[p] = __expf(s * 5.0f);
        atomicOr(&g_mask[(size_t)i*MASKW + (j>>5)], 1u << (j & 31));
        atomicOr(&g_mask[(size_t)j*MASKW + (i>>5)], 1u << (i & 31));
        g_flags[i] = 1; g_flags[j] = 1;
    }
}

// ---------------- compact needed rows (warp-aggregated atomics) --------------
__global__ void k_compact() {
    int r = blockIdx.x * 256 + threadIdx.x;
    int f = (r < B) ? g_flags[r] : 0;
    unsigned bal = __ballot_sync(0xffffffffu, f);
    int lane = threadIdx.x & 31;
    int base = 0;
    if (lane == 0 && bal) base = atomicAdd(&g_NR, __popc(bal));
    base = __shfl_sync(0xffffffffu, base, 0);
    if (f) g_rows[base + __popc(bal & ((1u << lane) - 1u))] = r;
}

// =================== HMMA GEMM -> u16 keys of cos ============================
__global__ void __launch_bounds__(128) k_gemm_mma() {
    int nr = g_NR;
    int rb = blockIdx.y, cb = blockIdx.x;
    if (rb * 128 >= nr) return;
    extern __shared__ __align__(16) char dsm[];
    __shared__ int rows_s[128];
    int t = threadIdx.x;
    {
        int s = rb*128 + t;
        rows_s[t] = (s < nr) ? g_rows[s] : g_rows[0];
    }
    __syncthreads();
    uint32_t sb = smem_u32(dsm);

    #pragma unroll
    for (int c = 0; c < 2; ++c) {
        uint32_t stg = sb + c*STAGE_BYTES;
        #pragma unroll
        for (int i = 0; i < 16; ++i) {
            int q = t + i*128;
            int row = q >> 4, seg = q & 15;
            cp_async16(stg + row*(LDC*2) + seg*16,
                       &g_Eh[(size_t)rows_s[row]*D + c*128 + seg*8]);
            cp_async16(stg + CHUNK_BYTES + row*(LDC*2) + seg*16,
                       &g_Eh[(size_t)(cb*128 + row)*D + c*128 + seg*8]);
        }
        asm volatile("cp.async.commit_group;" ::: "memory");
    }

    int wid = t >> 5, lane = t & 31;
    int wm = wid >> 1, wn = wid & 1;
    float acc[4][8][4];
    #pragma unroll
    for (int mt = 0; mt < 4; ++mt)
        #pragma unroll
        for (int nt = 0; nt < 8; ++nt)
            #pragma unroll
            for (int q = 0; q < 4; ++q) acc[mt][nt][q] = 0.f;

    #pragma unroll
    for (int c = 0; c < 2; ++c) {
        if (c == 0) asm volatile("cp.async.wait_group 1;" ::: "memory");
        else        asm volatile("cp.async.wait_group 0;" ::: "memory");
        __syncthreads();
        uint32_t Ab = sb + c*STAGE_BYTES;
        uint32_t Bb = Ab + CHUNK_BYTES;
        #pragma unroll
        for (int kt = 0; kt < 8; ++kt) {
            int k0 = kt*16;
            uint32_t a[4][4], bfr[4][4];
            #pragma unroll
            for (int mt = 0; mt < 4; ++mt) {
                uint32_t ad = Ab + (uint32_t)(wm*64 + mt*16 + (lane & 15))*(LDC*2)
                                 + (uint32_t)(k0 + (lane >> 4)*8)*2;
                ldsm_x4(a[mt], ad);
            }
            #pragma unroll
            for (int n2 = 0; n2 < 4; ++n2) {
                int q = lane >> 3, l8 = lane & 7;
                int rowb = wn*64 + n2*16 + ((q >> 1) << 3) + l8;
                uint32_t bd = Bb + (uint32_t)rowb*(LDC*2) + (uint32_t)(k0 + (q & 1)*8)*2;
                ldsm_x4(bfr[n2], bd);
            }
            #pragma unroll
            for (int mt = 0; mt < 4; ++mt)
                #pragma unroll
                for (int nt = 0; nt < 8; ++nt) {
                    uint32_t b2[2] = { bfr[nt>>1][(nt&1)*2], bfr[nt>>1][(nt&1)*2 + 1] };
                    mma16816(acc[mt][nt], a[mt], b2);
                }
        }
    }

    int lr = lane >> 2, lc2 = (lane & 3) * 2;
    #pragma unroll
    for (int mt = 0; mt < 4; ++mt)
        #pragma unroll
        for (int h = 0; h < 2; ++h) {
            int lrow = wm*64 + mt*16 + lr + h*8;
            int sl = rb*128 + lrow;
            if (sl >= nr) continue;
            int r = rows_s[lrow];
            unsigned mw0 = g_mask[(size_t)r*MASKW + cb*4 + wn*2];
            unsigned mw1 = g_mask[(size_t)r*MASKW + cb*4 + wn*2 + 1];
            size_t ob = (size_t)sl*B + (size_t)(cb*128 + wn*64);
            #pragma unroll
            for (int nt = 0; nt < 8; ++nt) {
                int bpos = nt*8 + lc2;
                unsigned mw = (bpos < 32) ? mw0 : mw1;
                int bit = bpos & 31;
                unsigned short k0 = ((mw >> bit) & 1u)
                    ? (unsigned short)KEY_MASKED : enc_key(acc[mt][nt][h*2]);
                unsigned short k1 = ((mw >> (bit+1)) & 1u)
                    ? (unsigned short)KEY_MASKED : enc_key(acc[mt][nt][h*2 + 1]);
                *(unsigned*)&g_KEY[ob + bpos] = (unsigned)k0 | ((unsigned)k1 << 16);
            }
        }
}

// ---------------- per-row: rank-6553 key -> S --------------------------------
__global__ void __launch_bounds__(256) k_select() {
    __shared__ unsigned short sv[B];      // 16 KB
    __shared__ unsigned hist[256];
    __shared__ unsigned wsum[8];
    __shared__ unsigned sb1, sustar;
    __shared__ int skrem;
    __shared__ float red[256];
    int slot = blockIdx.x;
    if (slot >= g_NR) return;
    int t = threadIdx.x, lane = t & 31, wid = t >> 5;
    const uint4* src = (const uint4*)&g_KEY[(size_t)slot*B];
    uint4* dst = (uint4*)sv;
    for (int i = t; i < B*2/16; i += 256) dst[i] = src[i];
    hist[t] = 0;
    __syncthreads();
    const unsigned* sw = (const unsigned*)sv;
    const int K = 6553;                   // S = sum of values >= v[6553]
    // pass 1: high byte, warp-aggregated
    for (int i = t; i < B/2; i += 256) {
        unsigned v = sw[i];
        hist_add(hist, (v >> 8) & 255u, lane);
        hist_add(hist, v >> 24, lane);
    }
    __syncthreads();
    {
        unsigned cin = scan256(hist, wsum, t, lane, wid);
        unsigned cex = cin - hist[t];
        if (cin > (unsigned)K && cex <= (unsigned)K) { sb1 = (unsigned)t; skrem = K - (int)cex; }
    }
    __syncthreads();
    unsigned b1 = sb1; int k2 = skrem;
    hist[t] = 0;
    __syncthreads();
    // pass 2: low byte among b1, warp-aggregated
    for (int i = t; i < B/2; i += 256) {
        unsigned v = sw[i];
        unsigned c0 = (((v >> 8) & 255u) == b1) ? (v & 255u) : 0xFFFFFFFFu;
        unsigned c1 = ((v >> 24) == b1) ? ((v >> 16) & 255u) : 0xFFFFFFFFu;
        hist_add(hist, c0, lane);
        hist_add(hist, c1, lane);
    }
    __syncthreads();
    {
        unsigned cin = scan256(hist, wsum, t, lane, wid);
        unsigned cex = cin - hist[t];
        if (cin > (unsigned)k2 && cex <= (unsigned)k2) sustar = (b1 << 8) | (unsigned)t;
    }
    __syncthreads();
    unsigned ustar = sustar;
    float s = 0.f;
    for (int i = t; i < B/2; i += 256) {
        unsigned v = sw[i];
        unsigned klo = v & 0xFFFFu, khi = v >> 16;
        if (klo >= ustar) s += __expf(5.0f * dec_key(klo));
        if (khi >= ustar) s += __expf(5.0f * dec_key(khi));
    }
    red[t] = s; __syncthreads();
    for (int o = 128; o > 0; o >>= 1) { if (t < o) red[t] += red[t+o]; __syncthreads(); }
    if (t == 0) g_S[g_rows[slot]] = red[0];
}

// ---------------- fused tail: pair threshold + moments + closed-form loss ----
__global__ void __launch_bounds__(256) k_tail(const int* __restrict__ pp,
                                              float* __restrict__ out) {
    __shared__ unsigned pv[P];
    __shared__ unsigned hist[256];
    __shared__ unsigned spre; __shared__ int skrem;
    __shared__ double redd[256];
    __shared__ double sm[5];
    int t = threadIdx.x;
    for (int c = t; c < P; c += 256) pv[c] = __float_as_uint(g_pos[c]);
    if (t == 0) { spre = 0u; skrem = 819; }
    __syncthreads();
    // exact fp32 radix select of k=819 (one block; cost irrelevant)
    for (int shift = 24; shift >= 0; shift -= 8) {
        hist[t] = 0u;
        __syncthreads();
        unsigned pre = spre;
        unsigned hm  = (shift == 24) ? 0u : (0xFFFFFFFFu << (shift + 8));
        for (int c = t; c < P; c += 256) {
            unsigned u = pv[c];
            if ((u & hm) == pre) atomicAdd(&hist[(u >> shift) & 255], 1u);
        }
        __syncthreads();
        #pragma unroll
        for (int o = 1; o < 256; o <<= 1) {
            unsigned v = (t >= o) ? hist[t-o] : 0u; __syncthreads();
            hist[t] += v; __syncthreads();
        }
        unsigned kr  = (unsigned)skrem;
        unsigned cin = hist[t];
        unsigned cex = t ? hist[t-1] : 0u;
        __syncthreads();
        if (cin > kr && cex <= kr) {
            spre  = pre | ((unsigned)t << shift);
            skrem = (int)(kr - cex);
        }
        __syncthreads();
    }
    float thr = __uint_as_float(spre);
    // moments over active pairs
    double m[5] = {0, 0, 0, 0, 0};   // kact, P1, P2, P3, sum log pos
    for (int p = t; p < P; p += 256) {
        float v = __uint_as_float(pv[p]);
        if (v <= thr) {
            double dv = (double)v;
            m[0] += 1.0; m[1] += dv; m[2] += dv*dv; m[3] += dv*dv*dv; m[4] += log(dv);
        }
    }
    #pragma unroll
    for (int q = 0; q < 5; ++q) {
        redd[t] = m[q]; __syncthreads();
        for (int o = 128; o > 0; o >>= 1) { if (t < o) redd[t] += redd[t+o]; __syncthreads(); }
        if (t == 0) sm[q] = redd[0];
        __syncthreads();
    }
    double kact = sm[0], P1 = sm[1], P2 = sm[2], P3 = sm[3], L = sm[4];
    // loss: sum over both sides of every pair
    double acc = 0.0;
    for (int s = t; s < 2*P; s += 256) {
        int pidx = s >> 1, side = s & 1;
        double S = (double)g_S[pp[pidx*2 + side]];
        if ((double)thr / S < 0.02) {
            double inv = 1.0 / S;
            acc += kact*log(S) - L + P1*inv - 0.5*P2*inv*inv + (1.0/3.0)*P3*inv*inv*inv;
        } else {
            for (int p = 0; p < P; ++p) {
                float pvv = __uint_as_float(pv[p]);
                if (pvv <= thr) acc += log1p(S / (double)pvv);
            }
        }
    }
    redd[t] = acc; __syncthreads();
    for (int o = 128; o > 0; o >>= 1) { if (t < o) redd[t] += redd[t+o]; __syncthreads(); }
    if (t == 0) out[0] = (float)(redd[0] / (2.0 * (double)P));
}

// ---------------- launch -----------------------------------------------------
extern "C" void kernel_launch(void* const* d_in, const int* in_sizes, int n_in,
                              void* d_out, int out_size) {
    const float* emb;
    const int*   pairs;
    if (in_sizes[0] == B*D) { emb = (const float*)d_in[0]; pairs = (const int*)d_in[1]; }
    else                    { emb = (const float*)d_in[1]; pairs = (const int*)d_in[0]; }
    float* out = (float*)d_out;

    cudaFuncSetAttribute(k_gemm_mma, cudaFuncAttributeMaxDynamicSharedMemorySize, GEMM_SMEM);

    k_clear    <<<(B*MASKW + 255)/256, 256>>>();
    k_normalize<<<B, 256>>>(emb);
    k_pairs    <<<P/8, 256>>>(pairs);
    k_compact  <<<B/256, 256>>>();
    k_gemm_mma <<<dim3(64, 64), 128, GEMM_SMEM>>>();
    k_select   <<<B, 256>>>();
    k_tail     <<<1, 256>>>(pairs, out);
}

// round 7
// speedup vs baseline: 1.1890x; 1.1890x over previous
#include <cuda_runtime.h>
#include <cuda_fp16.h>
#include <math.h>
#include <stdint.h>

#define B 8192
#define D 256
#define P 4096
#define MASKW 256                      /* B/32 mask words per row */
#define LDC 136                        /* chunk smem stride in halves (128+8) */
#define CHUNK_BYTES (128*LDC*2)        /* 34816 per matrix per stage */
#define STAGE_BYTES (2*CHUNK_BYTES)    /* A+B: 69632 */
#define GEMM_SMEM   (2*STAGE_BYTES)    /* 139264 */

// ---------------- device globals (no runtime allocation allowed) -------------
__device__ float    g_E[B*D];                    // normalized fp32 (8 MB)
__device__ __half   g_Eh[B*D];                   // normalized fp16 (4 MB)
__device__ unsigned g_mask[(size_t)B*MASKW];     // B x B bitmap (8 MB)
__device__ int      g_flags[B];
__device__ int      g_rows[B];
__device__ int      g_NR;
__device__ unsigned short g_KEY[(size_t)B*B];    // u16 ordered cos keys (128 MB)
__device__ float    g_S[B];
__device__ float    g_pos[P];

// ---------------- helpers ----------------------------------------------------
__device__ __forceinline__ uint32_t smem_u32(const void* p) {
    uint32_t a;
    asm("{ .reg .u64 t; cvta.to.shared.u64 t, %1; cvt.u32.u64 %0, t; }" : "=r"(a) : "l"(p));
    return a;
}
__device__ __forceinline__ void cp_async16(uint32_t dst, const void* src) {
    asm volatile("cp.async.cg.shared.global [%0], [%1], 16;" :: "r"(dst), "l"(src));
}
__device__ __forceinline__ void ldsm_x4(uint32_t* r, uint32_t addr) {
    asm volatile("ldmatrix.sync.aligned.m8n8.x4.shared.b16 {%0,%1,%2,%3}, [%4];"
        : "=r"(r[0]), "=r"(r[1]), "=r"(r[2]), "=r"(r[3]) : "r"(addr));
}
__device__ __forceinline__ void mma16816(float* c, const uint32_t* a, const uint32_t* b) {
    asm volatile(
        "mma.sync.aligned.m16n8k16.row.col.f32.f16.f16.f32 "
        "{%0,%1,%2,%3}, {%4,%5,%6,%7}, {%8,%9}, {%0,%1,%2,%3};"
        : "+f"(c[0]), "+f"(c[1]), "+f"(c[2]), "+f"(c[3])
        : "r"(a[0]), "r"(a[1]), "r"(a[2]), "r"(a[3]), "r"(b[0]), "r"(b[1]));
}
// order-preserving u16 key of fp16 value
__device__ __forceinline__ unsigned short enc_key(float c) {
    unsigned short h = __half_as_ushort(__float2half_rn(c));
    return (h & 0x8000) ? (unsigned short)(~h) : (unsigned short)(h | 0x8000);
}
__device__ __forceinline__ float dec_key(unsigned k) {
    unsigned short h = (k & 0x8000u) ? (unsigned short)(k & 0x7FFFu) : (unsigned short)(~k);
    return __half2float(__ushort_as_half(h));
}
#define KEY_MASKED 0x03FFu   /* enc(-inf): decodes to -inf, exp -> 0 */

// ---------------- clear ------------------------------------------------------
__global__ void k_clear() {
    int idx = blockIdx.x * 256 + threadIdx.x;
    if (idx < B*MASKW) g_mask[idx] = 0u;
    if (idx < B)       g_flags[idx] = 0;
    if (idx == 0)      g_NR = 0;
}

// ---------------- normalize + fp16 copy + diagonal mask ----------------------
__global__ void k_normalize(const float* __restrict__ emb) {
    int r = blockIdx.x, t = threadIdx.x;
    __shared__ float red[256];
    float x = emb[r*D + t];
    red[t] = x * x;
    __syncthreads();
    for (int o = 128; o > 0; o >>= 1) { if (t < o) red[t] += red[t+o]; __syncthreads(); }
    float nrm = fmaxf(sqrtf(red[0]), 1e-8f);
    float e = x / nrm;
    g_E [r*D + t] = e;
    g_Eh[r*D + t] = __float2half_rn(e);
    if (t == 0) g_mask[(size_t)r*MASKW + (r>>5)] = (1u << (r & 31));
}

// ---------------- pairs: exact fp32 pos, mask bits, row flags ----------------
__global__ void k_pairs(const int* __restrict__ pp) {
    int w = threadIdx.x >> 5, lane = threadIdx.x & 31;
    int p = blockIdx.x * 8 + w;
    if (p >= P) return;
    int i = pp[p*2], j = pp[p*2+1];
    const float* ei = &g_E[(size_t)i*D];
    const float* ej = &g_E[(size_t)j*D];
    float s = 0.f;
    #pragma unroll
    for (int q = 0; q < 8; q++) { int d = lane + 32*q; s += ei[d] * ej[d]; }
    #pragma unroll
    for (int o = 16; o > 0; o >>= 1) s += __shfl_xor_sync(0xffffffffu, s, o);
    if (lane == 0) {
        g_pos[p] = __expf(s * 5.0f);
        atomicOr(&g_mask[(size_t)i*MASKW + (j>>5)], 1u << (j & 31));
        atomicOr(&g_mask[(size_t)j*MASKW + (i>>5)], 1u << (i & 31));
        g_flags[i] = 1; g_flags[j] = 1;
    }
}

// ---------------- compact needed rows (warp-aggregated atomics) --------------
__global__ void k_compact() {
    int r = blockIdx.x * 256 + threadIdx.x;
    int f = (r < B) ? g_flags[r] : 0;
    unsigned bal = __ballot_sync(0xffffffffu, f);
    int lane = threadIdx.x & 31;
    int base = 0;
    if (lane == 0 && bal) base = atomicAdd(&g_NR, __popc(bal));
    base = __shfl_sync(0xffffffffu, base, 0);
    if (f) g_rows[base + __popc(bal & ((1u << lane) - 1u))] = r;
}

// =================== HMMA GEMM -> u16 keys of cos ============================
__global__ void __launch_bounds__(128) k_gemm_mma() {
    int nr = g_NR;
    int rb = blockIdx.y, cb = blockIdx.x;
    if (rb * 128 >= nr) return;
    extern __shared__ __align__(16) char dsm[];
    __shared__ int rows_s[128];
    int t = threadIdx.x;
    {
        int s = rb*128 + t;
        rows_s[t] = (s < nr) ? g_rows[s] : g_rows[0];
    }
    __syncthreads();
    uint32_t sb = smem_u32(dsm);

    #pragma unroll
    for (int c = 0; c < 2; ++c) {
        uint32_t stg = sb + c*STAGE_BYTES;
        #pragma unroll
        for (int i = 0; i < 16; ++i) {
            int q = t + i*128;
            int row = q >> 4, seg = q & 15;
            cp_async16(stg + row*(LDC*2) + seg*16,
                       &g_Eh[(size_t)rows_s[row]*D + c*128 + seg*8]);
            cp_async16(stg + CHUNK_BYTES + row*(LDC*2) + seg*16,
                       &g_Eh[(size_t)(cb*128 + row)*D + c*128 + seg*8]);
        }
        asm volatile("cp.async.commit_group;" ::: "memory");
    }

    int wid = t >> 5, lane = t & 31;
    int wm = wid >> 1, wn = wid & 1;
    float acc[4][8][4];
    #pragma unroll
    for (int mt = 0; mt < 4; ++mt)
        #pragma unroll
        for (int nt = 0; nt < 8; ++nt)
            #pragma unroll
            for (int q = 0; q < 4; ++q) acc[mt][nt][q] = 0.f;

    #pragma unroll
    for (int c = 0; c < 2; ++c) {
        if (c == 0) asm volatile("cp.async.wait_group 1;" ::: "memory");
        else        asm volatile("cp.async.wait_group 0;" ::: "memory");
        __syncthreads();
        uint32_t Ab = sb + c*STAGE_BYTES;
        uint32_t Bb = Ab + CHUNK_BYTES;
        #pragma unroll
        for (int kt = 0; kt < 8; ++kt) {
            int k0 = kt*16;
            uint32_t a[4][4], bfr[4][4];
            #pragma unroll
            for (int mt = 0; mt < 4; ++mt) {
                uint32_t ad = Ab + (uint32_t)(wm*64 + mt*16 + (lane & 15))*(LDC*2)
                                 + (uint32_t)(k0 + (lane >> 4)*8)*2;
                ldsm_x4(a[mt], ad);
            }
            #pragma unroll
            for (int n2 = 0; n2 < 4; ++n2) {
                int q = lane >> 3, l8 = lane & 7;
                int rowb = wn*64 + n2*16 + ((q >> 1) << 3) + l8;
                uint32_t bd = Bb + (uint32_t)rowb*(LDC*2) + (uint32_t)(k0 + (q & 1)*8)*2;
                ldsm_x4(bfr[n2], bd);
            }
            #pragma unroll
            for (int mt = 0; mt < 4; ++mt)
                #pragma unroll
                for (int nt = 0; nt < 8; ++nt) {
                    uint32_t b2[2] = { bfr[nt>>1][(nt&1)*2], bfr[nt>>1][(nt&1)*2 + 1] };
                    mma16816(acc[mt][nt], a[mt], b2);
                }
        }
    }

    int lr = lane >> 2, lc2 = (lane & 3) * 2;
    #pragma unroll
    for (int mt = 0; mt < 4; ++mt)
        #pragma unroll
        for (int h = 0; h < 2; ++h) {
            int lrow = wm*64 + mt*16 + lr + h*8;
            int sl = rb*128 + lrow;
            if (sl >= nr) continue;
            int r = rows_s[lrow];
            unsigned mw0 = g_mask[(size_t)r*MASKW + cb*4 + wn*2];
            unsigned mw1 = g_mask[(size_t)r*MASKW + cb*4 + wn*2 + 1];
            size_t ob = (size_t)sl*B + (size_t)(cb*128 + wn*64);
            #pragma unroll
            for (int nt = 0; nt < 8; ++nt) {
                int bpos = nt*8 + lc2;
                unsigned mw = (bpos < 32) ? mw0 : mw1;
                int bit = bpos & 31;
                unsigned short k0 = ((mw >> bit) & 1u)
                    ? (unsigned short)KEY_MASKED : enc_key(acc[mt][nt][h*2]);
                unsigned short k1 = ((mw >> (bit+1)) & 1u)
                    ? (unsigned short)KEY_MASKED : enc_key(acc[mt][nt][h*2 + 1]);
                *(unsigned*)&g_KEY[ob + bpos] = (unsigned)k0 | ((unsigned)k1 << 16);
            }
        }
}

// ---------------- per-row: register-resident bisection -> v[6553] -> S -------
// Keys live in 16 packed registers per thread; 16-step bisection on the u16
// key value with popc-SIMD counting; no atomics, no histograms, no smem data.
__global__ void __launch_bounds__(256) k_select() {
    __shared__ unsigned wred[8];
    __shared__ unsigned bflag;
    __shared__ float fred[8];
    int slot = blockIdx.x;
    if (slot >= g_NR) return;
    int t = threadIdx.x, lane = t & 31, wid = t >> 5;

    unsigned w[16];
    const uint4* src = (const uint4*)&g_KEY[(size_t)slot*B];
    #pragma unroll
    for (int q = 0; q < 4; ++q) {
        uint4 v = src[t + q*256];
        w[q*4+0] = v.x; w[q*4+1] = v.y; w[q*4+2] = v.z; w[q*4+3] = v.w;
    }

    const unsigned KTH = 1639u;   // need largest u with count(>= u) >= 1639
    unsigned cur = 0u;
    #pragma unroll
    for (int bit = 15; bit >= 0; --bit) {
        unsigned cand  = cur | (1u << bit);
        unsigned cand2 = cand | (cand << 16);
        unsigned cnt = 0;
        #pragma unroll
        for (int q = 0; q < 16; ++q)
            cnt += __popc(__vcmpgeu2(w[q], cand2));   // 16 per matching half
        #pragma unroll
        for (int o = 16; o > 0; o >>= 1)
            cnt += __shfl_xor_sync(0xffffffffu, cnt, o);
        if (lane == 0) wred[wid] = cnt;
        __syncthreads();
        if (t == 0) {
            unsigned tot = 0;
            #pragma unroll
            for (int i = 0; i < 8; ++i) tot += wred[i];
            bflag = (tot >= (KTH << 4)) ? 1u : 0u;    // counts are x16 from popc
        }
        __syncthreads();
        if (bflag) cur = cand;
    }

    // S = sum of exp(5*cos) over keys >= cur  (cur == key of v[6553])
    float s = 0.f;
    #pragma unroll
    for (int q = 0; q < 16; ++q) {
        unsigned klo = w[q] & 0xFFFFu, khi = w[q] >> 16;
        if (klo >= cur) s += __expf(5.0f * dec_key(klo));
        if (khi >= cur) s += __expf(5.0f * dec_key(khi));
    }
    #pragma unroll
    for (int o = 16; o > 0; o >>= 1)
        s += __shfl_xor_sync(0xffffffffu, s, o);
    if (lane == 0) fred[wid] = s;
    __syncthreads();
    if (t == 0) {
        float tot = 0.f;
        #pragma unroll
        for (int i = 0; i < 8; ++i) tot += fred[i];
        g_S[g_rows[slot]] = tot;
    }
}

// ---------------- fused tail: pair threshold + moments + closed-form loss ----
__global__ void __launch_bounds__(256) k_tail(const int* __restrict__ pp,
                                              float* __restrict__ out) {
    __shared__ unsigned pv[P];
    __shared__ unsigned hist[256];
    __shared__ unsigned spre; __shared__ int skrem;
    __shared__ double redd[256];
    __shared__ double sm[5];
    int t = threadIdx.x;
    for (int c = t; c < P; c += 256) pv[c] = __float_as_uint(g_pos[c]);
    if (t == 0) { spre = 0u; skrem = 819; }
    __syncthreads();
    for (int shift = 24; shift >= 0; shift -= 8) {
        hist[t] = 0u;
        __syncthreads();
        unsigned pre = spre;
        unsigned hm  = (shift == 24) ? 0u : (0xFFFFFFFFu << (shift + 8));
        for (int c = t; c < P; c += 256) {
            unsigned u = pv[c];
            if ((u & hm) == pre) atomicAdd(&hist[(u >> shift) & 255], 1u);
        }
        __syncthreads();
        #pragma unroll
        for (int o = 1; o < 256; o <<= 1) {
            unsigned v = (t >= o) ? hist[t-o] : 0u; __syncthreads();
            hist[t] += v; __syncthreads();
        }
        unsigned kr  = (unsigned)skrem;
        unsigned cin = hist[t];
        unsigned cex = t ? hist[t-1] : 0u;
        __syncthreads();
        if (cin > kr && cex <= kr) {
            spre  = pre | ((unsigned)t << shift);
            skrem = (int)(kr - cex);
        }
        __syncthreads();
    }
    float thr = __uint_as_float(spre);
    double m[5] = {0, 0, 0, 0, 0};   // kact, P1, P2, P3, sum log pos
    for (int p = t; p < P; p += 256) {
        float v = __uint_as_float(pv[p]);
        if (v <= thr) {
            double dv = (double)v;
            m[0] += 1.0; m[1] += dv; m[2] += dv*dv; m[3] += dv*dv*dv; m[4] += log(dv);
        }
    }
    #pragma unroll
    for (int q = 0; q < 5; ++q) {
        redd[t] = m[q]; __syncthreads();
        for (int o = 128; o > 0; o >>= 1) { if (t < o) redd[t] += redd[t+o]; __syncthreads(); }
        if (t == 0) sm[q] = redd[0];
        __syncthreads();
    }
    double kact = sm[0], P1 = sm[1], P2 = sm[2], P3 = sm[3], L = sm[4];
    double acc = 0.0;
    for (int s = t; s < 2*P; s += 256) {
        int pidx = s >> 1, side = s & 1;
        double S = (double)g_S[pp[pidx*2 + side]];
        if ((double)thr / S < 0.02) {
            double inv = 1.0 / S;
            acc += kact*log(S) - L + P1*inv - 0.5*P2*inv*inv + (1.0/3.0)*P3*inv*inv*inv;
        } else {
            for (int p = 0; p < P; ++p) {
                float pvv = __uint_as_float(pv[p]);
                if (pvv <= thr) acc += log1p(S / (double)pvv);
            }
        }
    }
    redd[t] = acc; __syncthreads();
    for (int o = 128; o > 0; o >>= 1) { if (t < o) redd[t] += redd[t+o]; __syncthreads(); }
    if (t == 0) out[0] = (float)(redd[0] / (2.0 * (double)P));
}

// ---------------- launch -----------------------------------------------------
extern "C" void kernel_launch(void* const* d_in, const int* in_sizes, int n_in,
                              void* d_out, int out_size) {
    const float* emb;
    const int*   pairs;
    if (in_sizes[0] == B*D) { emb = (const float*)d_in[0]; pairs = (const int*)d_in[1]; }
    else                    { emb = (const float*)d_in[1]; pairs = (const int*)d_in[0]; }
    float* out = (float*)d_out;

    cudaFuncSetAttribute(k_gemm_mma, cudaFuncAttributeMaxDynamicSharedMemorySize, GEMM_SMEM);

    k_clear    <<<(B*MASKW + 255)/256, 256>>>();
    k_normalize<<<B, 256>>>(emb);
    k_pairs    <<<P/8, 256>>>(pairs);
    k_compact  <<<B/256, 256>>>();
    k_gemm_mma <<<dim3(64, 64), 128, GEMM_SMEM>>>();
    k_select   <<<B, 256>>>();
    k_tail     <<<1, 256>>>(pairs, out);
}